// round 16
// baseline (speedup 1.0000x reference)
#include <cuda_runtime.h>
#include <cuda_fp16.h>
#include <math.h>
#include <stdint.h>

#define NTOK 4096
#define DM   256
#define HD   64
#define KSTR 72   // fp16 smem stride (halves): 64 + 8 pad
#define GSTR 72

// ---------------- scratch ----------------------------------------------------
__device__ __half g_qh[NTOK * DM], g_kh[NTOK * DM], g_vh[NTOK * DM];
__device__ __half g_WQ[DM * DM], g_WK[DM * DM], g_WV[DM * DM], g_WO[DM * DM];
__device__ __half g_Qh[NTOK * DM];   // projected Q (scaled by 0.125*log2e)
__device__ __half g_Kh[NTOK * DM];
__device__ __half g_Vh[NTOK * DM];
__device__ float  g_Op[2][NTOK * DM];  // split-K partial O (unnormalized, fp32)
__device__ float  g_L[2][4 * NTOK];    // split-K partial row sums, [s][h*NTOK+row]
__device__ float  g_cos[NTOK * 32];
__device__ float  g_sin[NTOK * 32];

// ---------------- helpers ----------------------------------------------------
__device__ __forceinline__ uint32_t smem_u32(const void* p) {
    uint32_t a;
    asm("{ .reg .u64 t; cvta.to.shared.u64 t, %1; cvt.u32.u64 %0, t; }" : "=r"(a) : "l"(p));
    return a;
}
__device__ __forceinline__ void cp16(uint32_t dst, const void* src) {
    asm volatile("cp.async.ca.shared.global [%0], [%1], 16;" :: "r"(dst), "l"(src));
}
#define CP_COMMIT() asm volatile("cp.async.commit_group;" ::: "memory")
#define CP_WAIT(n)  asm volatile("cp.async.wait_group %0;" :: "n"(n) : "memory")

__device__ __forceinline__ void ldsm4(uint32_t a, uint32_t& r0, uint32_t& r1,
                                      uint32_t& r2, uint32_t& r3) {
    asm volatile("ldmatrix.sync.aligned.m8n8.x4.shared.b16 {%0,%1,%2,%3}, [%4];"
                 : "=r"(r0), "=r"(r1), "=r"(r2), "=r"(r3) : "r"(a));
}
__device__ __forceinline__ void ldsm4t(uint32_t a, uint32_t& r0, uint32_t& r1,
                                       uint32_t& r2, uint32_t& r3) {
    asm volatile("ldmatrix.sync.aligned.m8n8.x4.trans.shared.b16 {%0,%1,%2,%3}, [%4];"
                 : "=r"(r0), "=r"(r1), "=r"(r2), "=r"(r3) : "r"(a));
}
__device__ __forceinline__ void mma16816(float* c, uint32_t a0, uint32_t a1,
                                         uint32_t a2, uint32_t a3,
                                         uint32_t b0, uint32_t b1) {
    asm volatile(
        "mma.sync.aligned.m16n8k16.row.col.f32.f16.f16.f32 "
        "{%0,%1,%2,%3},{%4,%5,%6,%7},{%8,%9},{%0,%1,%2,%3};"
        : "+f"(c[0]), "+f"(c[1]), "+f"(c[2]), "+f"(c[3])
        : "r"(a0), "r"(a1), "r"(a2), "r"(a3), "r"(b0), "r"(b1));
}
__device__ __forceinline__ uint32_t pack2(float lo, float hi) {
    __half2 h = __floats2half2_rn(lo, hi);
    return *(uint32_t*)&h;
}

// ---------------- prep: cvt fp32->fp16 (inputs+weights) + rope table ---------
__global__ void prep_kernel(const float* q, const float* k, const float* v,
                            const float* wq, const float* wk,
                            const float* wv, const float* wo) {
    const int NM4 = NTOK * DM / 4;
    const int W4  = DM * DM / 4;
    const int CVT = 3 * NM4 + 4 * W4;
    int i = blockIdx.x * blockDim.x + threadIdx.x;
    if (i < CVT) {
        const float* src;
        __half* dst;
        int off;
        if (i < 3 * NM4) {
            int t = i / NM4; off = i - t * NM4;
            src = (t == 0) ? q : (t == 1) ? k : v;
            dst = (t == 0) ? g_qh : (t == 1) ? g_kh : g_vh;
        } else {
            int j = i - 3 * NM4;
            int t = j / W4; off = j - t * W4;
            src = (t == 0) ? wq : (t == 1) ? wk : (t == 2) ? wv : wo;
            dst = (t == 0) ? g_WQ : (t == 1) ? g_WK : (t == 2) ? g_WV : g_WO;
        }
        float4 f = ((const float4*)src)[off];
        uint2 h;
        h.x = pack2(f.x, f.y);
        h.y = pack2(f.z, f.w);
        ((uint2*)dst)[off] = h;
    } else {
        int idx = i - CVT;
        if (idx >= NTOK * 32) return;
        int n = idx >> 5;
        int j = idx & 31;
        float pos = (j < 16) ? (float)(n & 63) : (float)(n >> 6);
        int jj = j & 15;
        float f = expf(-(float)jj * (9.210340371976184f / 16.0f));
        float s, c;
        sincosf(pos * f, &s, &c);
        g_cos[idx] = c;
        g_sin[idx] = s;
    }
}

// ---------------- QKV projection GEMM (R6 double-buffered, fp16 out) ---------
#define GEMM_SMEM 57600
__global__ void __launch_bounds__(256)
gemm_qkv_kernel(const float* __restrict__ bq, const float* __restrict__ bk,
                const float* __restrict__ bv) {
    const int z = blockIdx.z;
    const __half* A = (z == 0) ? g_qh : (z == 1) ? g_kh : g_vh;
    const __half* W = (z == 0) ? g_WQ : (z == 1) ? g_WK : g_WV;
    const float* bias = (z == 0) ? bq : (z == 1) ? bk : bv;
    __half* Ch = (z == 0) ? g_Qh : (z == 1) ? g_Kh : g_Vh;
    const int applyRope = (z < 2);
    const float outScale = (z == 0) ? 0.18033688011112042f : 1.0f;  // 0.125*log2(e)

    extern __shared__ __align__(16) char gsm[];
    const uint32_t base = smem_u32(gsm);
    const int tid = threadIdx.x, wid = tid >> 5, L = tid & 31;
    const int bm = blockIdx.x * 128, bn = blockIdx.y * 64;

    const uint32_t aBuf[2] = {base, base + 18432};
    const uint32_t wBuf[2] = {base + 36864, base + 47232};

    auto loadChunk = [&](int k0, int b) {
        #pragma unroll
        for (int t = 0; t < 4; t++) {
            int it = tid + t * 256;
            int row = it >> 3, ch = it & 7;
            cp16(aBuf[b] + (row * GSTR + ch * 8) * 2, &A[(bm + row) * DM + k0 + ch * 8]);
        }
        #pragma unroll
        for (int t = 0; t < 2; t++) {
            int it = tid + t * 256;
            int row = it >> 3, ch = it & 7;
            cp16(wBuf[b] + (row * GSTR + ch * 8) * 2, &W[(k0 + row) * DM + bn + ch * 8]);
        }
        CP_COMMIT();
    };

    loadChunk(0, 0);

    const int brow = ((L >> 3) & 1) * 8 + (L & 7);
    const int bcol = (L >> 4) * 8;
    float acc[8][4] = {};

    #pragma unroll
    for (int kk = 0; kk < 4; kk++) {
        CP_WAIT(0);
        __syncthreads();
        if (kk < 3) loadChunk((kk + 1) * 64, (kk + 1) & 1);
        const uint32_t aA = aBuf[kk & 1];
        const uint32_t aW = wBuf[kk & 1];
        const uint32_t qaddr = aA + ((wid * 16 + (L & 15)) * GSTR + (L >> 4) * 8) * 2;
        #pragma unroll
        for (int kc4 = 0; kc4 < 4; kc4++) {
            const int kc = kc4 * 16;
            uint32_t a0, a1, a2, a3;
            ldsm4(qaddr + kc * 2, a0, a1, a2, a3);
            #pragma unroll
            for (int np = 0; np < 4; np++) {
                const int n0 = np * 16;
                uint32_t b0, b1, b2, b3;
                ldsm4t(aW + ((kc + brow) * GSTR + n0 + bcol) * 2, b0, b1, b2, b3);
                mma16816(acc[np * 2], a0, a1, a2, a3, b0, b1);
                mma16816(acc[np * 2 + 1], a0, a1, a2, a3, b2, b3);
            }
        }
        __syncthreads();
    }

    const int r0 = bm + wid * 16 + (L >> 2);
    const int r1 = r0 + 8;
    #pragma unroll
    for (int j = 0; j < 8; j++) {
        const int col = bn + j * 8 + (L & 3) * 2;
        float v0 = acc[j][0] + bias[col], v1 = acc[j][1] + bias[col + 1];
        float v2 = acc[j][2] + bias[col], v3 = acc[j][3] + bias[col + 1];
        if (applyRope) {
            int j0 = (col & 63) >> 1;
            float c0 = g_cos[r0 * 32 + j0], s0 = g_sin[r0 * 32 + j0];
            float c1 = g_cos[r1 * 32 + j0], s1 = g_sin[r1 * 32 + j0];
            float t0 = v0 * c0 - v1 * s0, t1 = v0 * s0 + v1 * c0;
            float t2 = v2 * c1 - v3 * s1, t3 = v2 * s1 + v3 * c1;
            v0 = t0; v1 = t1; v2 = t2; v3 = t3;
        }
        *(uint32_t*)&Ch[r0 * DM + col] = pack2(v0 * outScale, v1 * outScale);
        *(uint32_t*)&Ch[r1 * DM + col] = pack2(v2 * outScale, v3 * outScale);
    }
}

// ---------------- output GEMM with fused split-K combine + normalize ---------
// A = (g_Op[0]+g_Op[1]) * inv(l), converted fp16 in smem. All W up front.
// smem: A 4x18432 @0 | W 4x9216 @73728 | invL 4x128 f32 @110592. 112640 B.
#define GEMMF_SMEM 112640
__global__ void __launch_bounds__(256)
gemm_out_kernel(const float* __restrict__ bo, float* __restrict__ out) {
    extern __shared__ __align__(16) char gsm[];
    const uint32_t base = smem_u32(gsm);
    const uint32_t aB = base;
    const uint32_t wB = base + 73728;
    float* sInv = (float*)(gsm + 110592);
    const int tid = threadIdx.x, wid = tid >> 5, L = tid & 31;
    const int bm = blockIdx.x * 128, bn = blockIdx.y * 64;

    // ---- W: all 4 chunks via cp.async (in flight during A convert) ----
    #pragma unroll
    for (int t = 0; t < 8; t++) {
        int it = tid + t * 256;
        int r = it >> 3, cg = it & 7;
        cp16(wB + (r >> 6) * 9216 + ((r & 63) * GSTR + cg * 8) * 2,
             &g_WO[r * DM + bn + cg * 8]);
    }
    CP_COMMIT();

    // ---- invL[h][row] = 1 / (l0 + l1) ----
    #pragma unroll
    for (int t = 0; t < 2; t++) {
        int idx = tid + t * 256;
        int h = idx >> 7, row = idx & 127;
        sInv[idx] = 1.0f / (g_L[0][h * NTOK + bm + row] + g_L[1][h * NTOK + bm + row]);
    }
    __syncthreads();

    // ---- A: combine partials, normalize, pack fp16 into smem ----
    #pragma unroll
    for (int t = 0; t < 16; t++) {
        int it = tid + t * 256;
        int row = it >> 5, cg = it & 31;
        int col = cg * 8;
        int h = cg >> 3;
        const float* p0 = &g_Op[0][(bm + row) * DM + col];
        const float* p1 = &g_Op[1][(bm + row) * DM + col];
        float4 x0 = *(const float4*)p0;
        float4 x1 = *(const float4*)(p0 + 4);
        float4 y0 = *(const float4*)p1;
        float4 y1 = *(const float4*)(p1 + 4);
        float inv = sInv[h * 128 + row];
        uint4 u;
        u.x = pack2((x0.x + y0.x) * inv, (x0.y + y0.y) * inv);
        u.y = pack2((x0.z + y0.z) * inv, (x0.w + y0.w) * inv);
        u.z = pack2((x1.x + y1.x) * inv, (x1.y + y1.y) * inv);
        u.w = pack2((x1.z + y1.z) * inv, (x1.w + y1.w) * inv);
        uint32_t dst = aB + h * 18432 + (row * GSTR + (col & 63)) * 2;
        asm volatile("st.shared.v4.b32 [%0], {%1,%2,%3,%4};"
                     :: "r"(dst), "r"(u.x), "r"(u.y), "r"(u.z), "r"(u.w) : "memory");
    }
    CP_WAIT(0);
    __syncthreads();

    // ---- MMA loop: K=256 in 4 chunks, all smem-resident ----
    const int brow = ((L >> 3) & 1) * 8 + (L & 7);
    const int bcol = (L >> 4) * 8;
    float acc[8][4] = {};
    #pragma unroll
    for (int kk = 0; kk < 4; kk++) {
        const uint32_t qaddr = aB + kk * 18432 +
                               ((wid * 16 + (L & 15)) * GSTR + (L >> 4) * 8) * 2;
        const uint32_t aW = wB + kk * 9216;
        #pragma unroll
        for (int kc4 = 0; kc4 < 4; kc4++) {
            const int kc = kc4 * 16;
            uint32_t a0, a1, a2, a3;
            ldsm4(qaddr + kc * 2, a0, a1, a2, a3);
            #pragma unroll
            for (int np = 0; np < 4; np++) {
                const int n0 = np * 16;
                uint32_t b0, b1, b2, b3;
                ldsm4t(aW + ((kc + brow) * GSTR + n0 + bcol) * 2, b0, b1, b2, b3);
                mma16816(acc[np * 2], a0, a1, a2, a3, b0, b1);
                mma16816(acc[np * 2 + 1], a0, a1, a2, a3, b2, b3);
            }
        }
    }

    // ---- epilogue: bias + fp32 store ----
    const int r0 = bm + wid * 16 + (L >> 2);
    const int r1 = r0 + 8;
    #pragma unroll
    for (int j = 0; j < 8; j++) {
        const int col = bn + j * 8 + (L & 3) * 2;
        *(float2*)&out[r0 * DM + col] =
            make_float2(acc[j][0] + bo[col], acc[j][1] + bo[col + 1]);
        *(float2*)&out[r1 * DM + col] =
            make_float2(acc[j][2] + bo[col], acc[j][3] + bo[col + 1]);
    }
}

// ---------------- fp16 flash attention: BM=64, 4 warps, split-K x2 -----------
// grid (64 q-tiles, 4 heads, 2 key-splits), 128 threads. Each CTA: 2048 keys.
__global__ void __launch_bounds__(128)
attn_kernel() {
    __shared__ __half sQ[64 * KSTR];
    __shared__ __half sK[2][64 * KSTR];
    __shared__ __half sV[2][64 * KSTR];

    const int tid = threadIdx.x;
    const int wid = tid >> 5;
    const int L = tid & 31;
    const int h = blockIdx.y;
    const int s = blockIdx.z;
    const int q0 = blockIdx.x * 64;
    const int kt0 = s * 2048;
    const int cb = h * HD;
    const int m0 = wid * 16;

    const uint32_t qb = smem_u32(sQ);
    const uint32_t kb0 = smem_u32(sK[0]);
    const uint32_t vb0 = smem_u32(sV[0]);
    const uint32_t tileB = 64 * KSTR * 2;

    {
        #pragma unroll
        for (int t = 0; t < 4; t++) {
            int it = tid + t * 128;
            int row = it >> 3, ch = it & 7;
            cp16(qb + (row * KSTR + ch * 8) * 2, &g_Qh[(q0 + row) * DM + cb + ch * 8]);
        }
        CP_COMMIT();
        #pragma unroll
        for (int t = 0; t < 4; t++) {
            int it = tid + t * 128;
            int row = it >> 3, ch = it & 7;
            cp16(kb0 + (row * KSTR + ch * 8) * 2, &g_Kh[(kt0 + row) * DM + cb + ch * 8]);
        }
        #pragma unroll
        for (int t = 0; t < 4; t++) {
            int it = tid + t * 128;
            int row = it >> 3, ch = it & 7;
            cp16(vb0 + (row * KSTR + ch * 8) * 2, &g_Vh[(kt0 + row) * DM + cb + ch * 8]);
        }
        CP_COMMIT();
    }

    const uint32_t qaddr = qb + ((m0 + (L & 15)) * KSTR + (L >> 4) * 8) * 2;
    const int krow = (L >> 4) * 8 + (L & 7);
    const int kcol = ((L >> 3) & 1) * 8;
    const int vrow = ((L >> 3) & 1) * 8 + (L & 7);
    const int vcol = (L >> 4) * 8;
    const uint32_t onesB = (L < 4) ? 0x3C003C00u : 0u;  // ones in col 0

    // ---- hoist loop-invariant Q fragments ----
    CP_WAIT(1);
    __syncthreads();
    uint32_t qf[4][4];
    #pragma unroll
    for (int kc4 = 0; kc4 < 4; kc4++)
        ldsm4(qaddr + kc4 * 32, qf[kc4][0], qf[kc4][1], qf[kc4][2], qf[kc4][3]);

    float oa[8][4] = {};
    float lacc[4] = {};

    for (int i = 0; i < 32; i++) {
        const int buf = i & 1;
        if (i + 1 < 32) {
            const int nb = (i + 1) & 1;
            const uint32_t kbn = kb0 + nb * tileB;
            const uint32_t vbn = vb0 + nb * tileB;
            const int kt = kt0 + (i + 1) * 64;
            #pragma unroll
            for (int t = 0; t < 4; t++) {
                int it = tid + t * 128;
                int row = it >> 3, ch = it & 7;
                cp16(kbn + (row * KSTR + ch * 8) * 2, &g_Kh[(kt + row) * DM + cb + ch * 8]);
            }
            #pragma unroll
            for (int t = 0; t < 4; t++) {
                int it = tid + t * 128;
                int row = it >> 3, ch = it & 7;
                cp16(vbn + (row * KSTR + ch * 8) * 2, &g_Vh[(kt + row) * DM + cb + ch * 8]);
            }
            CP_COMMIT();
            CP_WAIT(1);
        } else {
            CP_WAIT(0);
        }
        __syncthreads();

        const uint32_t kb = kb0 + buf * tileB;
        const uint32_t vb = vb0 + buf * tileB;

        // ---- S' = (Q*log2e/8) @ K^T ----
        float sc[8][4] = {};
        #pragma unroll
        for (int kc4 = 0; kc4 < 4; kc4++) {
            const int kc = kc4 * 16;
            #pragma unroll
            for (int np = 0; np < 4; np++) {
                const int n0 = np * 16;
                uint32_t b0, b1, b2, b3;
                ldsm4(kb + ((n0 + krow) * KSTR + kc + kcol) * 2, b0, b1, b2, b3);
                mma16816(sc[np * 2], qf[kc4][0], qf[kc4][1], qf[kc4][2], qf[kc4][3], b0, b1);
                mma16816(sc[np * 2 + 1], qf[kc4][0], qf[kc4][1], qf[kc4][2], qf[kc4][3], b2, b3);
            }
        }

        // ---- P = 2^(S') packed f16x2 ----
        uint32_t pf[8][2];
        #pragma unroll
        for (int j = 0; j < 8; j++) {
            __half2 e0 = h2exp2(__floats2half2_rn(sc[j][0], sc[j][1]));
            __half2 e1 = h2exp2(__floats2half2_rn(sc[j][2], sc[j][3]));
            pf[j][0] = *(uint32_t*)&e0;
            pf[j][1] = *(uint32_t*)&e1;
        }

        // ---- O += P @ V ; l += P @ ones ----
        #pragma unroll
        for (int c = 0; c < 4; c++) {
            const int kc = c * 16;
            const uint32_t a0 = pf[2 * c][0], a1 = pf[2 * c][1];
            const uint32_t a2 = pf[2 * c + 1][0], a3 = pf[2 * c + 1][1];
            #pragma unroll
            for (int dp = 0; dp < 4; dp++) {
                const int n0 = dp * 16;
                uint32_t b0, b1, b2, b3;
                ldsm4t(vb + ((kc + vrow) * KSTR + n0 + vcol) * 2, b0, b1, b2, b3);
                mma16816(oa[dp * 2], a0, a1, a2, a3, b0, b1);
                mma16816(oa[dp * 2 + 1], a0, a1, a2, a3, b2, b3);
            }
            mma16816(lacc, a0, a1, a2, a3, onesB, onesB);
        }
        __syncthreads();
    }

    // ---- store unnormalized partials ----
    const int r0 = q0 + m0 + (L >> 2);
    const int cc = (L & 3) * 2;
    float* op = g_Op[s];
    #pragma unroll
    for (int j = 0; j < 8; j++) {
        *(float2*)&op[r0 * DM + cb + j * 8 + cc] = make_float2(oa[j][0], oa[j][1]);
        *(float2*)&op[(r0 + 8) * DM + cb + j * 8 + cc] = make_float2(oa[j][2], oa[j][3]);
    }
    if ((L & 3) == 0) {
        g_L[s][h * NTOK + r0] = lacc[0];
        g_L[s][h * NTOK + r0 + 8] = lacc[2];
    }
}

// ---------------- launch -----------------------------------------------------
extern "C" void kernel_launch(void* const* d_in, const int* in_sizes, int n_in,
                              void* d_out, int out_size) {
    const float* q  = (const float*)d_in[0];
    const float* k  = (const float*)d_in[1];
    const float* v  = (const float*)d_in[2];
    const float* wq = (const float*)d_in[3];
    const float* bq = (const float*)d_in[4];
    const float* wk = (const float*)d_in[5];
    const float* bk = (const float*)d_in[6];
    const float* wv = (const float*)d_in[7];
    const float* bv = (const float*)d_in[8];
    const float* wo = (const float*)d_in[9];
    const float* bo = (const float*)d_in[10];
    float* out = (float*)d_out;

    cudaFuncSetAttribute(gemm_qkv_kernel, cudaFuncAttributeMaxDynamicSharedMemorySize, GEMM_SMEM);
    cudaFuncSetAttribute(gemm_out_kernel, cudaFuncAttributeMaxDynamicSharedMemorySize, GEMMF_SMEM);

    const int prepTot = 3 * (NTOK * DM / 4) + 4 * (DM * DM / 4) + NTOK * 32;
    prep_kernel<<<(prepTot + 255) / 256, 256>>>(q, k, v, wq, wk, wv, wo);

    gemm_qkv_kernel<<<dim3(NTOK / 128, DM / 64, 3), 256, GEMM_SMEM>>>(bq, bk, bv);

    attn_kernel<<<dim3(NTOK / 64, 4, 2), 128>>>();

    gemm_out_kernel<<<dim3(NTOK / 128, DM / 64), 256, GEMMF_SMEM>>>(bo, out);
}

// round 17
// speedup vs baseline: 1.0017x; 1.0017x over previous
#include <cuda_runtime.h>
#include <cuda_fp16.h>
#include <math.h>
#include <stdint.h>

#define NTOK 4096
#define DM   256
#define HD   64
#define KSTR 72   // fp16 smem stride (halves): 64 + 8 pad
#define GSTR 72

// ---------------- scratch ----------------------------------------------------
__device__ __half g_qh[NTOK * DM], g_kh[NTOK * DM], g_vh[NTOK * DM];
__device__ __half g_WQ[DM * DM], g_WK[DM * DM], g_WV[DM * DM], g_WO[DM * DM];
__device__ __half g_Qh[NTOK * DM];   // projected Q (scaled by 0.125*log2e)
__device__ __half g_Kh[NTOK * DM];
__device__ __half g_Vh[NTOK * DM];
__device__ __half g_Oh[NTOK * DM];   // combined attention output (fp16)
__device__ float  g_Op[2][NTOK * DM];  // split-K partial O (unnormalized, fp32)
__device__ float  g_L[2][4 * NTOK];    // split-K partial row sums, [s][h*NTOK+row]
__device__ int    g_cnt[4 * 64];       // last-CTA counters per (head, q-tile)
__device__ float  g_cos[NTOK * 32];
__device__ float  g_sin[NTOK * 32];

// ---------------- helpers ----------------------------------------------------
__device__ __forceinline__ uint32_t smem_u32(const void* p) {
    uint32_t a;
    asm("{ .reg .u64 t; cvta.to.shared.u64 t, %1; cvt.u32.u64 %0, t; }" : "=r"(a) : "l"(p));
    return a;
}
__device__ __forceinline__ void cp16(uint32_t dst, const void* src) {
    asm volatile("cp.async.ca.shared.global [%0], [%1], 16;" :: "r"(dst), "l"(src));
}
#define CP_COMMIT() asm volatile("cp.async.commit_group;" ::: "memory")
#define CP_WAIT(n)  asm volatile("cp.async.wait_group %0;" :: "n"(n) : "memory")

__device__ __forceinline__ void ldsm4(uint32_t a, uint32_t& r0, uint32_t& r1,
                                      uint32_t& r2, uint32_t& r3) {
    asm volatile("ldmatrix.sync.aligned.m8n8.x4.shared.b16 {%0,%1,%2,%3}, [%4];"
                 : "=r"(r0), "=r"(r1), "=r"(r2), "=r"(r3) : "r"(a));
}
__device__ __forceinline__ void ldsm4t(uint32_t a, uint32_t& r0, uint32_t& r1,
                                       uint32_t& r2, uint32_t& r3) {
    asm volatile("ldmatrix.sync.aligned.m8n8.x4.trans.shared.b16 {%0,%1,%2,%3}, [%4];"
                 : "=r"(r0), "=r"(r1), "=r"(r2), "=r"(r3) : "r"(a));
}
__device__ __forceinline__ void mma16816(float* c, uint32_t a0, uint32_t a1,
                                         uint32_t a2, uint32_t a3,
                                         uint32_t b0, uint32_t b1) {
    asm volatile(
        "mma.sync.aligned.m16n8k16.row.col.f32.f16.f16.f32 "
        "{%0,%1,%2,%3},{%4,%5,%6,%7},{%8,%9},{%0,%1,%2,%3};"
        : "+f"(c[0]), "+f"(c[1]), "+f"(c[2]), "+f"(c[3])
        : "r"(a0), "r"(a1), "r"(a2), "r"(a3), "r"(b0), "r"(b1));
}
__device__ __forceinline__ uint32_t pack2(float lo, float hi) {
    __half2 h = __floats2half2_rn(lo, hi);
    return *(uint32_t*)&h;
}

// ---------------- prep: cvt fp32->fp16 + rope table + counter reset ----------
__global__ void prep_kernel(const float* q, const float* k, const float* v,
                            const float* wq, const float* wk,
                            const float* wv, const float* wo) {
    const int NM4 = NTOK * DM / 4;
    const int W4  = DM * DM / 4;
    const int CVT = 3 * NM4 + 4 * W4;
    int i = blockIdx.x * blockDim.x + threadIdx.x;
    if (i < 256) g_cnt[i] = 0;
    if (i < CVT) {
        const float* src;
        __half* dst;
        int off;
        if (i < 3 * NM4) {
            int t = i / NM4; off = i - t * NM4;
            src = (t == 0) ? q : (t == 1) ? k : v;
            dst = (t == 0) ? g_qh : (t == 1) ? g_kh : g_vh;
        } else {
            int j = i - 3 * NM4;
            int t = j / W4; off = j - t * W4;
            src = (t == 0) ? wq : (t == 1) ? wk : (t == 2) ? wv : wo;
            dst = (t == 0) ? g_WQ : (t == 1) ? g_WK : (t == 2) ? g_WV : g_WO;
        }
        float4 f = ((const float4*)src)[off];
        uint2 h;
        h.x = pack2(f.x, f.y);
        h.y = pack2(f.z, f.w);
        ((uint2*)dst)[off] = h;
    } else {
        int idx = i - CVT;
        if (idx >= NTOK * 32) return;
        int n = idx >> 5;
        int j = idx & 31;
        float pos = (j < 16) ? (float)(n & 63) : (float)(n >> 6);
        int jj = j & 15;
        float f = expf(-(float)jj * (9.210340371976184f / 16.0f));
        float s, c;
        sincosf(pos * f, &s, &c);
        g_cos[idx] = c;
        g_sin[idx] = s;
    }
}

// ---------------- fp16 tensor GEMM body (R6/R14 double-buffered) -------------
#define GEMM_SMEM 57600
__device__ __forceinline__ void gemm16_body(
    const __half* __restrict__ A, const __half* __restrict__ W,
    const float* __restrict__ bias, float* __restrict__ Cf,
    __half* __restrict__ Ch, int applyRope, float outScale) {
    extern __shared__ __align__(16) char gsm[];
    const uint32_t base = smem_u32(gsm);
    const int tid = threadIdx.x, wid = tid >> 5, L = tid & 31;
    const int bm = blockIdx.x * 128, bn = blockIdx.y * 64;

    const uint32_t aBuf[2] = {base, base + 18432};
    const uint32_t wBuf[2] = {base + 36864, base + 47232};

    auto loadChunk = [&](int k0, int b) {
        #pragma unroll
        for (int t = 0; t < 4; t++) {
            int it = tid + t * 256;
            int row = it >> 3, ch = it & 7;
            cp16(aBuf[b] + (row * GSTR + ch * 8) * 2, &A[(bm + row) * DM + k0 + ch * 8]);
        }
        #pragma unroll
        for (int t = 0; t < 2; t++) {
            int it = tid + t * 256;
            int row = it >> 3, ch = it & 7;
            cp16(wBuf[b] + (row * GSTR + ch * 8) * 2, &W[(k0 + row) * DM + bn + ch * 8]);
        }
        CP_COMMIT();
    };

    loadChunk(0, 0);

    const int brow = ((L >> 3) & 1) * 8 + (L & 7);
    const int bcol = (L >> 4) * 8;
    float acc[8][4] = {};

    #pragma unroll
    for (int kk = 0; kk < 4; kk++) {
        CP_WAIT(0);
        __syncthreads();
        if (kk < 3) loadChunk((kk + 1) * 64, (kk + 1) & 1);
        const uint32_t aA = aBuf[kk & 1];
        const uint32_t aW = wBuf[kk & 1];
        const uint32_t qaddr = aA + ((wid * 16 + (L & 15)) * GSTR + (L >> 4) * 8) * 2;
        #pragma unroll
        for (int kc4 = 0; kc4 < 4; kc4++) {
            const int kc = kc4 * 16;
            uint32_t a0, a1, a2, a3;
            ldsm4(qaddr + kc * 2, a0, a1, a2, a3);
            #pragma unroll
            for (int np = 0; np < 4; np++) {
                const int n0 = np * 16;
                uint32_t b0, b1, b2, b3;
                ldsm4t(aW + ((kc + brow) * GSTR + n0 + bcol) * 2, b0, b1, b2, b3);
                mma16816(acc[np * 2], a0, a1, a2, a3, b0, b1);
                mma16816(acc[np * 2 + 1], a0, a1, a2, a3, b2, b3);
            }
        }
        __syncthreads();
    }

    const int r0 = bm + wid * 16 + (L >> 2);
    const int r1 = r0 + 8;
    #pragma unroll
    for (int j = 0; j < 8; j++) {
        const int col = bn + j * 8 + (L & 3) * 2;
        float v0 = acc[j][0] + bias[col], v1 = acc[j][1] + bias[col + 1];
        float v2 = acc[j][2] + bias[col], v3 = acc[j][3] + bias[col + 1];
        if (applyRope) {
            int j0 = (col & 63) >> 1;
            float c0 = g_cos[r0 * 32 + j0], s0 = g_sin[r0 * 32 + j0];
            float c1 = g_cos[r1 * 32 + j0], s1 = g_sin[r1 * 32 + j0];
            float t0 = v0 * c0 - v1 * s0, t1 = v0 * s0 + v1 * c0;
            float t2 = v2 * c1 - v3 * s1, t3 = v2 * s1 + v3 * c1;
            v0 = t0; v1 = t1; v2 = t2; v3 = t3;
        }
        if (Ch) {
            *(uint32_t*)&Ch[r0 * DM + col] = pack2(v0 * outScale, v1 * outScale);
            *(uint32_t*)&Ch[r1 * DM + col] = pack2(v2 * outScale, v3 * outScale);
        } else {
            *(float2*)&Cf[r0 * DM + col] = make_float2(v0, v1);
            *(float2*)&Cf[r1 * DM + col] = make_float2(v2, v3);
        }
    }
}

__global__ void __launch_bounds__(256)
gemm_qkv_kernel(const float* __restrict__ bq, const float* __restrict__ bk,
                const float* __restrict__ bv) {
    const int z = blockIdx.z;
    const __half* A = (z == 0) ? g_qh : (z == 1) ? g_kh : g_vh;
    const __half* W = (z == 0) ? g_WQ : (z == 1) ? g_WK : g_WV;
    const float* bias = (z == 0) ? bq : (z == 1) ? bk : bv;
    __half* C = (z == 0) ? g_Qh : (z == 1) ? g_Kh : g_Vh;
    const float sc = (z == 0) ? 0.18033688011112042f : 1.0f;  // 0.125*log2(e)
    gemm16_body(A, W, bias, nullptr, C, z < 2, sc);
}

__global__ void __launch_bounds__(256)
gemm_out_kernel(const float* __restrict__ bo, float* __restrict__ out) {
    gemm16_body(g_Oh, g_WO, bo, out, nullptr, 0, 1.0f);
}

// ---------------- fp16 flash attention: split-K x2, last-CTA combine ---------
// grid (64 q-tiles, 4 heads, 2 key-splits), 128 threads. Each CTA: 2048 keys.
// The second CTA (per q-tile,head) to finish combines partials -> g_Oh fp16.
__global__ void __launch_bounds__(128)
attn_kernel() {
    __shared__ __half sQ[64 * KSTR];
    __shared__ __half sK[2][64 * KSTR];
    __shared__ __half sV[2][64 * KSTR];
    __shared__ int sFlag;

    const int tid = threadIdx.x;
    const int wid = tid >> 5;
    const int L = tid & 31;
    const int h = blockIdx.y;
    const int s = blockIdx.z;
    const int q0 = blockIdx.x * 64;
    const int kt0 = s * 2048;
    const int cb = h * HD;
    const int m0 = wid * 16;

    const uint32_t qb = smem_u32(sQ);
    const uint32_t kb0 = smem_u32(sK[0]);
    const uint32_t vb0 = smem_u32(sV[0]);
    const uint32_t tileB = 64 * KSTR * 2;

    {
        #pragma unroll
        for (int t = 0; t < 4; t++) {
            int it = tid + t * 128;
            int row = it >> 3, ch = it & 7;
            cp16(qb + (row * KSTR + ch * 8) * 2, &g_Qh[(q0 + row) * DM + cb + ch * 8]);
        }
        CP_COMMIT();
        #pragma unroll
        for (int t = 0; t < 4; t++) {
            int it = tid + t * 128;
            int row = it >> 3, ch = it & 7;
            cp16(kb0 + (row * KSTR + ch * 8) * 2, &g_Kh[(kt0 + row) * DM + cb + ch * 8]);
        }
        #pragma unroll
        for (int t = 0; t < 4; t++) {
            int it = tid + t * 128;
            int row = it >> 3, ch = it & 7;
            cp16(vb0 + (row * KSTR + ch * 8) * 2, &g_Vh[(kt0 + row) * DM + cb + ch * 8]);
        }
        CP_COMMIT();
    }

    const uint32_t qaddr = qb + ((m0 + (L & 15)) * KSTR + (L >> 4) * 8) * 2;
    const int krow = (L >> 4) * 8 + (L & 7);
    const int kcol = ((L >> 3) & 1) * 8;
    const int vrow = ((L >> 3) & 1) * 8 + (L & 7);
    const int vcol = (L >> 4) * 8;
    const uint32_t onesB = (L < 4) ? 0x3C003C00u : 0u;  // ones in col 0

    // ---- hoist loop-invariant Q fragments ----
    CP_WAIT(1);
    __syncthreads();
    uint32_t qf[4][4];
    #pragma unroll
    for (int kc4 = 0; kc4 < 4; kc4++)
        ldsm4(qaddr + kc4 * 32, qf[kc4][0], qf[kc4][1], qf[kc4][2], qf[kc4][3]);

    float oa[8][4] = {};
    float lacc[4] = {};

    for (int i = 0; i < 32; i++) {
        const int buf = i & 1;
        if (i + 1 < 32) {
            const int nb = (i + 1) & 1;
            const uint32_t kbn = kb0 + nb * tileB;
            const uint32_t vbn = vb0 + nb * tileB;
            const int kt = kt0 + (i + 1) * 64;
            #pragma unroll
            for (int t = 0; t < 4; t++) {
                int it = tid + t * 128;
                int row = it >> 3, ch = it & 7;
                cp16(kbn + (row * KSTR + ch * 8) * 2, &g_Kh[(kt + row) * DM + cb + ch * 8]);
            }
            #pragma unroll
            for (int t = 0; t < 4; t++) {
                int it = tid + t * 128;
                int row = it >> 3, ch = it & 7;
                cp16(vbn + (row * KSTR + ch * 8) * 2, &g_Vh[(kt + row) * DM + cb + ch * 8]);
            }
            CP_COMMIT();
            CP_WAIT(1);
        } else {
            CP_WAIT(0);
        }
        __syncthreads();

        const uint32_t kb = kb0 + buf * tileB;
        const uint32_t vb = vb0 + buf * tileB;

        // ---- S' = (Q*log2e/8) @ K^T ----
        float sc[8][4] = {};
        #pragma unroll
        for (int kc4 = 0; kc4 < 4; kc4++) {
            const int kc = kc4 * 16;
            #pragma unroll
            for (int np = 0; np < 4; np++) {
                const int n0 = np * 16;
                uint32_t b0, b1, b2, b3;
                ldsm4(kb + ((n0 + krow) * KSTR + kc + kcol) * 2, b0, b1, b2, b3);
                mma16816(sc[np * 2], qf[kc4][0], qf[kc4][1], qf[kc4][2], qf[kc4][3], b0, b1);
                mma16816(sc[np * 2 + 1], qf[kc4][0], qf[kc4][1], qf[kc4][2], qf[kc4][3], b2, b3);
            }
        }

        // ---- P = 2^(S') packed f16x2 ----
        uint32_t pf[8][2];
        #pragma unroll
        for (int j = 0; j < 8; j++) {
            __half2 e0 = h2exp2(__floats2half2_rn(sc[j][0], sc[j][1]));
            __half2 e1 = h2exp2(__floats2half2_rn(sc[j][2], sc[j][3]));
            pf[j][0] = *(uint32_t*)&e0;
            pf[j][1] = *(uint32_t*)&e1;
        }

        // ---- O += P @ V ; l += P @ ones ----
        #pragma unroll
        for (int c = 0; c < 4; c++) {
            const int kc = c * 16;
            const uint32_t a0 = pf[2 * c][0], a1 = pf[2 * c][1];
            const uint32_t a2 = pf[2 * c + 1][0], a3 = pf[2 * c + 1][1];
            #pragma unroll
            for (int dp = 0; dp < 4; dp++) {
                const int n0 = dp * 16;
                uint32_t b0, b1, b2, b3;
                ldsm4t(vb + ((kc + vrow) * KSTR + n0 + vcol) * 2, b0, b1, b2, b3);
                mma16816(oa[dp * 2], a0, a1, a2, a3, b0, b1);
                mma16816(oa[dp * 2 + 1], a0, a1, a2, a3, b2, b3);
            }
            mma16816(lacc, a0, a1, a2, a3, onesB, onesB);
        }
        __syncthreads();
    }

    // ---- store unnormalized partials ----
    const int r0 = q0 + m0 + (L >> 2);
    const int cc = (L & 3) * 2;
    float* op = g_Op[s];
    #pragma unroll
    for (int j = 0; j < 8; j++) {
        *(float2*)&op[r0 * DM + cb + j * 8 + cc] = make_float2(oa[j][0], oa[j][1]);
        *(float2*)&op[(r0 + 8) * DM + cb + j * 8 + cc] = make_float2(oa[j][2], oa[j][3]);
    }
    if ((L & 3) == 0) {
        g_L[s][h * NTOK + r0] = lacc[0];
        g_L[s][h * NTOK + r0 + 8] = lacc[2];
    }

    // ---- last-CTA combine: second finisher merges partner partial -> g_Oh ---
    __threadfence();
    __syncthreads();
    if (tid == 0) sFlag = atomicAdd(&g_cnt[h * 64 + blockIdx.x], 1);
    __syncthreads();
    if (sFlag == 1) {
        const int sp = s ^ 1;
        const float* pp = g_Op[sp];
        const float lt0 = g_L[0][h * NTOK + r0] + g_L[1][h * NTOK + r0];
        const float lt1 = g_L[0][h * NTOK + r0 + 8] + g_L[1][h * NTOK + r0 + 8];
        const float inv0 = 1.0f / lt0;
        const float inv1 = 1.0f / lt1;
        #pragma unroll
        for (int j = 0; j < 8; j++) {
            float2 p0 = *(const float2*)&pp[r0 * DM + cb + j * 8 + cc];
            float2 p1 = *(const float2*)&pp[(r0 + 8) * DM + cb + j * 8 + cc];
            *(uint32_t*)&g_Oh[r0 * DM + cb + j * 8 + cc] =
                pack2((oa[j][0] + p0.x) * inv0, (oa[j][1] + p0.y) * inv0);
            *(uint32_t*)&g_Oh[(r0 + 8) * DM + cb + j * 8 + cc] =
                pack2((oa[j][2] + p1.x) * inv1, (oa[j][3] + p1.y) * inv1);
        }
    }
}

// ---------------- launch -----------------------------------------------------
extern "C" void kernel_launch(void* const* d_in, const int* in_sizes, int n_in,
                              void* d_out, int out_size) {
    const float* q  = (const float*)d_in[0];
    const float* k  = (const float*)d_in[1];
    const float* v  = (const float*)d_in[2];
    const float* wq = (const float*)d_in[3];
    const float* bq = (const float*)d_in[4];
    const float* wk = (const float*)d_in[5];
    const float* bk = (const float*)d_in[6];
    const float* wv = (const float*)d_in[7];
    const float* bv = (const float*)d_in[8];
    const float* wo = (const float*)d_in[9];
    const float* bo = (const float*)d_in[10];
    float* out = (float*)d_out;

    cudaFuncSetAttribute(gemm_qkv_kernel, cudaFuncAttributeMaxDynamicSharedMemorySize, GEMM_SMEM);
    cudaFuncSetAttribute(gemm_out_kernel, cudaFuncAttributeMaxDynamicSharedMemorySize, GEMM_SMEM);

    const int prepTot = 3 * (NTOK * DM / 4) + 4 * (DM * DM / 4) + NTOK * 32;
    prep_kernel<<<(prepTot + 255) / 256, 256>>>(q, k, v, wq, wk, wv, wo);

    gemm_qkv_kernel<<<dim3(NTOK / 128, DM / 64, 3), 256, GEMM_SMEM>>>(bq, bk, bv);

    attn_kernel<<<dim3(NTOK / 64, 4, 2), 128>>>();

    gemm_out_kernel<<<dim3(NTOK / 128, DM / 64), 256, GEMM_SMEM>>>(bo, out);
}